// round 9
// baseline (speedup 1.0000x reference)
#include <cuda_runtime.h>

// QueryEncDec: 2x128-layer scalar GRU (H=in=1), T=256, fused 256-layer wavefront.
// v9: 1 layer/thread (256 thr, 8 warps) but TWO TIME STEPS per iteration:
// lane l at iter s computes t=2(s-l) and 2(s-l)+1. Both x inputs arrive as a
// pair of shuffles from lane l-1's previous iteration -> handoff cost halved
// per cell. Warp boundaries: write-once smem pair buffers + named-barrier
// chunked publish (chunk = 4 iters = 8 t-values, lag 8). tanh.approx gates.
//
// out[0:256]   = dec_out  (layer 255 output at each t)
// out[256:384] = dec_h    (final hidden of global layers 128..255)

#define GRU_T 256
#define NW    8
#define KIT   4      // iterations per chunk (= 8 t-values)
#define NCH   40     // 40*4 = 160 >= 159 iterations

__device__ __forceinline__ float ftanh(float a) {
    float r; asm("tanh.approx.f32 %0, %1;" : "=f"(r) : "f"(a)); return r;
}

__global__ __launch_bounds__(256, 1)
void gru_wave_v9(const float* __restrict__ X,
                 const float* __restrict__ ewi, const float* __restrict__ ewh,
                 const float* __restrict__ ebi, const float* __restrict__ ebh,
                 const float* __restrict__ dwi, const float* __restrict__ dwh,
                 const float* __restrict__ dbi, const float* __restrict__ dbh,
                 float* __restrict__ out)
{
    const int tid  = threadIdx.x;
    const int l    = tid;          // global layer 0..255
    const int w    = tid >> 5;
    const int lane = tid & 31;

    __shared__ __align__(16) float xs[GRU_T];
    __shared__ __align__(16) float bb[NW - 1][GRU_T];   // boundary pairs
    __shared__ int rel_scratch[NW];

    if (tid < GRU_T) xs[tid] = X[tid];

    // per-layer scalar weights (torch gate order r,z,n)
    const bool  enc = (l < 128);
    const int   li  = enc ? l : (l - 128);
    const float* wi = enc ? ewi : dwi;
    const float* wh = enc ? ewh : dwh;
    const float* bi = enc ? ebi : dbi;
    const float* bh = enc ? ebh : dbh;

    const float wi_r = wi[li*3+0], wi_z = wi[li*3+1], wi_n = wi[li*3+2];
    const float wh_r = wh[li*3+0], wh_z = wh[li*3+1], wh_n = wh[li*3+2];
    const float bi_r = bi[li*3+0], bi_z = bi[li*3+1], bi_n = bi[li*3+2];
    const float bh_r = bh[li*3+0], bh_z = bh[li*3+1], bh_n = bh[li*3+2];

    // r,z: sigmoid(u) = 0.5 + 0.5*tanh(u/2) -> half-scaled args
    const float hwi_r = 0.5f * wi_r, hwh_r = 0.5f * wh_r;
    const float hb_r  = 0.5f * (bi_r + bh_r);
    const float hwi_z = 0.5f * wi_z, hwh_z = 0.5f * wh_z;
    const float hb_z  = 0.5f * (bi_z + bh_z);
    const float hwh_n = 0.5f * wh_n, hbh_n = 0.5f * bh_n;

    // state: hA/hB = this lane's outputs at t=2p, 2p+1 of the last iteration
    float hA = 0.0f, hB = 0.0f;
    // cell1 h-terms, precomputed from hB in the tail (h=0 initially)
    float nc_r = hb_r, nc_z = hb_z, ghn = hbh_n, hh = 0.0f;

    __syncthreads();

    const float* inbox  = (w == 0) ? xs : bb[w - 1];
    float*       outbox = (w < NW - 1) ? bb[w] : bb[0];
    const bool   is_prod = (lane == 31) && (w < NW - 1);
    const bool   is_last = (w == NW - 1) && (lane == 31);   // layer 255
    const unsigned rel_addr =
        (unsigned)__cvta_generic_to_shared(&rel_scratch[w]);

    #pragma unroll 1
    for (int ic = 0; ic < NCH; ++ic) {
        // consumer: wait for upstream t-chunk ic (pairs 4ic..4ic+3), prefetch
        if (w > 0 && ic < 32) {
            asm volatile("bar.sync %0, %1;" :: "r"(w), "r"(64) : "memory");
        }
        float pf[8];
        if (lane == 0 && ic < 32) {
            float4 va = *(const float4*)(inbox + ic * 8);
            float4 vb = *(const float4*)(inbox + ic * 8 + 4);
            pf[0]=va.x; pf[1]=va.y; pf[2]=va.z; pf[3]=va.w;
            pf[4]=vb.x; pf[5]=vb.y; pf[6]=vb.z; pf[7]=vb.w;
        }

        #pragma unroll
        for (int u = 0; u < KIT; ++u) {
            const int s = ic * KIT + u;
            const int p = s - lane;                     // pair index
            const bool valid = ((unsigned)p) < 128u;

            float xA = __shfl_up_sync(0xFFFFFFFFu, hA, 1);
            float xB = __shfl_up_sync(0xFFFFFFFFu, hB, 1);
            if (lane == 0) { xA = pf[2*u]; xB = pf[2*u + 1]; }

            // ---- cell 1: t = 2p, state = hB(prev), nc-terms precomputed ----
            const float t_r1 = ftanh(fmaf(hwi_r, xA, nc_r));
            const float t_z1 = ftanh(fmaf(hwi_z, xA, nc_z));
            const float xn1  = fmaf(wi_n, xA, bi_n);
            const float t_n1 = ftanh(fmaf(ghn, t_r1, xn1 + ghn));
            const float A1   = fmaf(-0.5f, t_z1, 0.5f);
            const float C1   = fmaf(hh, t_z1, hh);
            const float h1   = fmaf(A1, t_n1, C1);

            // ---- cell 2: t = 2p+1, state = h1, nc-terms inline ----
            const float ncr2 = fmaf(hwh_r, h1, hb_r);
            const float ncz2 = fmaf(hwh_z, h1, hb_z);
            const float ghn2 = fmaf(hwh_n, h1, hbh_n);
            const float hh2  = 0.5f * h1;
            const float t_r2 = ftanh(fmaf(hwi_r, xB, ncr2));
            const float t_z2 = ftanh(fmaf(hwi_z, xB, ncz2));
            const float xn2  = fmaf(wi_n, xB, bi_n);
            const float t_n2 = ftanh(fmaf(ghn2, t_r2, xn2 + ghn2));
            const float A2   = fmaf(-0.5f, t_z2, 0.5f);
            const float C2   = fmaf(hh2, t_z2, hh2);
            const float h2   = fmaf(A2, t_n2, C2);

            if (valid) { hA = h1; hB = h2; }

            if (is_prod && valid) {                     // pair store, off-chain
                float2 v; v.x = hA; v.y = hB;
                *(float2*)(outbox + 2 * p) = v;
            }

            // tail: cell1 h-terms for next iteration (from hB)
            nc_r = fmaf(hwh_r, hB, hb_r);
            nc_z = fmaf(hwh_z, hB, hb_z);
            ghn  = fmaf(hwh_n, hB, hbh_n);
            hh   = 0.5f * hB;

            if (is_last && valid) {                     // dec_out (layer 255)
                out[2 * p]     = hA;
                out[2 * p + 1] = hB;
            }
            if (valid && p == 127 && l >= 128)          // dec_h (t = 255)
                out[GRU_T + (l - 128)] = hB;
        }

        // producer: publish t-chunk ic-8 (pair 4(ic-8)+3 done at s=4ic-29)
        if (w < NW - 1 && ic >= 8) {
            if (is_prod) {
                asm volatile("st.release.cta.shared.b32 [%0], %1;"
                             :: "r"(rel_addr), "r"(ic) : "memory");
            }
            asm volatile("bar.arrive %0, %1;" :: "r"(w + 1), "r"(64) : "memory");
        }
    }
}

extern "C" void kernel_launch(void* const* d_in, const int* in_sizes, int n_in,
                              void* d_out, int out_size)
{
    const float* X   = (const float*)d_in[0];
    const float* ewi = (const float*)d_in[1];
    const float* ewh = (const float*)d_in[2];
    const float* ebi = (const float*)d_in[3];
    const float* ebh = (const float*)d_in[4];
    const float* dwi = (const float*)d_in[5];
    const float* dwh = (const float*)d_in[6];
    const float* dbi = (const float*)d_in[7];
    const float* dbh = (const float*)d_in[8];
    float* out = (float*)d_out;

    gru_wave_v9<<<1, 256>>>(X, ewi, ewh, ebi, ebh, dwi, dwh, dbi, dbh, out);
}

// round 11
// speedup vs baseline: 1.1405x; 1.1405x over previous
#include <cuda_runtime.h>

// QueryEncDec: 2x128-layer scalar GRU (H=in=1), T=256, fused 256-layer wavefront.
// v11 = v6 + steady-state specialization (chunks 4-30 unpredicated) + SAFE
// barrier protocol: producer publish is a blocking rendezvous (bar.sync on both
// sides), immune to producer/consumer speed mismatch (v8/v10 hang root cause:
// non-blocking bar.arrive double-firing into one phase when the steady-path
// producer outran a prologue consumer).
//
// out[0:256]   = dec_out  (layer 255 output at each t)
// out[256:384] = dec_h    (final hidden of global layers 128..255)

#define GRU_T 256
#define NW    8
#define KC    8
#define NCH   36     // 36*8 = 288 >= 287 inner steps

__device__ __forceinline__ float ftanh(float a) {
    float r; asm("tanh.approx.f32 %0, %1;" : "=f"(r) : "f"(a)); return r;
}

struct GruW {
    float hwi_r, hwh_r, hb_r;
    float hwi_z, hwh_z, hb_z;
    float wi_n,  bi_n,  hwh_n, hbh_n;
};

template<bool STEADY>
__device__ __forceinline__ void run_chunk(
    int ic, int w, int lane, int l, bool is_prod, bool is_last,
    const float* __restrict__ inbox, float* __restrict__ outbox,
    float* __restrict__ out, const GruW& W,
    float& h, float& nc_r, float& nc_z, float& ghn_h, float& hhalf)
{
    // consumer side of rendezvous: wait for upstream t-chunk ic, then prefetch
    if (w > 0 && ic < GRU_T / KC) {
        asm volatile("bar.sync %0, %1;" :: "r"(w), "r"(64) : "memory");
    }
    float pf[KC];
    if (lane == 0 && ic < GRU_T / KC) {
        float4 va = *(const float4*)(inbox + ic * KC);
        float4 vb = *(const float4*)(inbox + ic * KC + 4);
        pf[0]=va.x; pf[1]=va.y; pf[2]=va.z; pf[3]=va.w;
        pf[4]=vb.x; pf[5]=vb.y; pf[6]=vb.z; pf[7]=vb.w;
    }

    #pragma unroll
    for (int u = 0; u < KC; ++u) {
        const int j = ic * KC + u;
        const int t = j - lane;

        float x = __shfl_up_sync(0xFFFFFFFFu, h, 1);
        if (lane == 0) x = pf[u];

        const float t_r = ftanh(fmaf(W.hwi_r, x, nc_r));
        const float t_z = ftanh(fmaf(W.hwi_z, x, nc_z));
        const float xn  = fmaf(W.wi_n, x, W.bi_n);
        const float t_n = ftanh(fmaf(ghn_h, t_r, xn + ghn_h));
        const float A   = fmaf(-0.5f, t_z, 0.5f);
        const float C   = fmaf(hhalf, t_z, hhalf);
        const float hn  = fmaf(A, t_n, C);

        if (STEADY) {
            h = hn;                                   // unconditional (t in [1,247])
            if (is_prod) outbox[t] = h;
            if (is_last) out[t]    = h;               // dec_out
        } else {
            const bool valid = (t >= 0) && (t < GRU_T);
            if (valid) h = hn;
            if (is_prod && valid) outbox[t] = h;
            if (is_last && valid) out[t]    = h;                        // dec_out
            if (t == GRU_T - 1 && l >= 128) out[GRU_T + (l - 128)] = h; // dec_h
        }

        nc_r  = fmaf(W.hwh_r, h, W.hb_r);
        nc_z  = fmaf(W.hwh_z, h, W.hb_z);
        ghn_h = fmaf(W.hwh_n, h, W.hbh_n);
        hhalf = 0.5f * h;
    }

    // producer side of rendezvous: publish t-chunk ic-4 (blocking bar.sync —
    // safe under any warp speed skew; STS drained by BAR semantics)
    if (w < NW - 1 && ic >= 4) {
        asm volatile("bar.sync %0, %1;" :: "r"(w + 1), "r"(64) : "memory");
    }
}

__global__ __launch_bounds__(256, 1)
void gru_wave_v11(const float* __restrict__ X,
                  const float* __restrict__ ewi, const float* __restrict__ ewh,
                  const float* __restrict__ ebi, const float* __restrict__ ebh,
                  const float* __restrict__ dwi, const float* __restrict__ dwh,
                  const float* __restrict__ dbi, const float* __restrict__ dbh,
                  float* __restrict__ out)
{
    const int tid  = threadIdx.x;
    const int l    = tid;          // global layer 0..255
    const int w    = tid >> 5;
    const int lane = tid & 31;

    __shared__ __align__(16) float xs[GRU_T];
    __shared__ __align__(16) float bb[NW - 1][GRU_T];

    if (tid < GRU_T) xs[tid] = X[tid];

    // per-layer scalar weights (torch gate order r,z,n)
    const bool  enc = (l < 128);
    const int   li  = enc ? l : (l - 128);
    const float* wi = enc ? ewi : dwi;
    const float* wh = enc ? ewh : dwh;
    const float* bi = enc ? ebi : dbi;
    const float* bh = enc ? ebh : dbh;

    const float wi_r = wi[li*3+0], wi_z = wi[li*3+1], wi_n = wi[li*3+2];
    const float wh_r = wh[li*3+0], wh_z = wh[li*3+1], wh_n = wh[li*3+2];
    const float bi_r = bi[li*3+0], bi_z = bi[li*3+1], bi_n = bi[li*3+2];
    const float bh_r = bh[li*3+0], bh_z = bh[li*3+1], bh_n = bh[li*3+2];

    GruW W;
    W.hwi_r = 0.5f * wi_r; W.hwh_r = 0.5f * wh_r; W.hb_r = 0.5f * (bi_r + bh_r);
    W.hwi_z = 0.5f * wi_z; W.hwh_z = 0.5f * wh_z; W.hb_z = 0.5f * (bi_z + bh_z);
    W.wi_n  = wi_n;        W.bi_n  = bi_n;
    W.hwh_n = 0.5f * wh_n; W.hbh_n = 0.5f * bh_n;

    float h     = 0.0f;
    float nc_r  = W.hb_r;
    float nc_z  = W.hb_z;
    float ghn_h = W.hbh_n;
    float hhalf = 0.0f;

    __syncthreads();

    const float* inbox  = (w == 0) ? xs : bb[w - 1];
    float*       outbox = (w < NW - 1) ? bb[w] : bb[0];
    const bool   is_prod = (lane == 31) && (w < NW - 1);
    const bool   is_last = (w == NW - 1) && (lane == 31);   // layer 255

    #pragma unroll 1
    for (int ic = 0; ic < 4; ++ic)
        run_chunk<false>(ic, w, lane, l, is_prod, is_last,
                         inbox, outbox, out, W, h, nc_r, nc_z, ghn_h, hhalf);

    #pragma unroll 1
    for (int ic = 4; ic < 31; ++ic)
        run_chunk<true>(ic, w, lane, l, is_prod, is_last,
                        inbox, outbox, out, W, h, nc_r, nc_z, ghn_h, hhalf);

    #pragma unroll 1
    for (int ic = 31; ic < NCH; ++ic)
        run_chunk<false>(ic, w, lane, l, is_prod, is_last,
                         inbox, outbox, out, W, h, nc_r, nc_z, ghn_h, hhalf);
}

extern "C" void kernel_launch(void* const* d_in, const int* in_sizes, int n_in,
                              void* d_out, int out_size)
{
    const float* X   = (const float*)d_in[0];
    const float* ewi = (const float*)d_in[1];
    const float* ewh = (const float*)d_in[2];
    const float* ebi = (const float*)d_in[3];
    const float* ebh = (const float*)d_in[4];
    const float* dwi = (const float*)d_in[5];
    const float* dwh = (const float*)d_in[6];
    const float* dbi = (const float*)d_in[7];
    const float* dbh = (const float*)d_in[8];
    float* out = (float*)d_out;

    gru_wave_v11<<<1, 256>>>(X, ewi, ewh, ebi, ebh, dwi, dwh, dbi, dbh, out);
}